// round 3
// baseline (speedup 1.0000x reference)
#include <cuda_runtime.h>
#include <math.h>
#include <stdint.h>

#define BSZ 8
#define CCH 512
#define TT  8192
#define NEL (BSZ*CCH*TT)   // 33554432
#define KW  3
#define WSZ (CCH*CCH*KW)   // 786432

typedef unsigned long long ull;

// ---------------- scratch (static device globals; no allocation) -------------
__device__ float g_act[NEL];
__device__ float g_c1[NEL];
__device__ float g_w1[WSZ];
__device__ float g_w2[WSZ];
__device__ float g_a2c[2*CCH];
__device__ float g_binv[2*CCH];

// ---------------- packed f32x2 helpers ---------------------------------------
__device__ __forceinline__ ull ffma2(ull a, ull b, ull c) {
    ull d;
    asm("fma.rn.f32x2 %0, %1, %2, %3;" : "=l"(d) : "l"(a), "l"(b), "l"(c));
    return d;
}
__device__ __forceinline__ ull pack2(float lo, float hi) {
    ull d;
    asm("mov.b64 %0, {%1, %2};" : "=l"(d) : "f"(lo), "f"(hi));
    return d;
}
__device__ __forceinline__ void unpack2(ull v, float& lo, float& hi) {
    asm("mov.b64 {%0, %1}, %2;" : "=f"(lo), "=f"(hi) : "l"(v));
}
__device__ __forceinline__ ull lds64(uint32_t addr) {
    ull v;
    asm("ld.shared.b64 %0, [%1];" : "=l"(v) : "r"(addr));
    return v;
}

// ---------------- kernel 1: weight norm + snake param precompute -------------
__global__ void wnorm_kernel(const float* __restrict__ v, const float* __restrict__ g,
                             float* __restrict__ w,
                             const float* __restrict__ alpha, const float* __restrict__ beta,
                             float* __restrict__ a2out, float* __restrict__ binvout)
{
    int co = blockIdx.x;
    const float* vc = v + co * (CCH * KW);
    float s = 0.f;
    for (int i = threadIdx.x; i < CCH * KW; i += 256) {
        float t = vc[i];
        s += t * t;
    }
    __shared__ float red[256];
    red[threadIdx.x] = s;
    __syncthreads();
    for (int off = 128; off > 0; off >>= 1) {
        if (threadIdx.x < off) red[threadIdx.x] += red[threadIdx.x + off];
        __syncthreads();
    }
    float scale = g[co] / sqrtf(red[0]);
    for (int i = threadIdx.x; i < CCH * KW; i += 256)
        w[co * (CCH * KW) + i] = vc[i] * scale;
    if (threadIdx.x == 0) {
        a2out[co]   = 2.f * expf(alpha[co]);
        binvout[co] = 1.f / (2.f * expf(beta[co]) + 1e-9f);
    }
}

// ---------------- kernel 2: fused SnakeBeta Activation1d (float4) ------------
// u0 = (t>0) ? 0.25*x[t-1] + 0.75*x[t] : x[t]
// u1 = 0.75*x[t] + 0.25*((t<T-1) ? x[t+1] : x[t])
// out = 0.5*(f(u0)+f(u1)),  f(u) = u + (1-cos(2a*u)) / (2b+eps)
__global__ void snake_act_kernel(const float4* __restrict__ in4,
                                 const float*  __restrict__ in,
                                 const float*  __restrict__ a2,
                                 const float*  __restrict__ binv,
                                 float4* __restrict__ out4)
{
    int idx4 = blockIdx.x * blockDim.x + threadIdx.x;
    if (idx4 >= NEL / 4) return;
    int base = idx4 * 4;
    int t = base & (TT - 1);
    int c = (base >> 13) & (CCH - 1);

    float4 xv = in4[idx4];
    float xm = (t > 0)           ? in[base - 1] : 0.f;
    float xp = (t + 4 < TT)      ? in[base + 4] : xv.w;

    float aa = a2[c];
    float bi = 0.5f * binv[c];

    float xs[6] = {xm, xv.x, xv.y, xv.z, xv.w, xp};
    float4 r;
    float* ro = &r.x;
#pragma unroll
    for (int p = 0; p < 4; p++) {
        float x0 = xs[p + 1];
        float u0 = (t + p > 0) ? fmaf(0.25f, xs[p], 0.75f * x0) : x0;
        float u1 = fmaf(0.25f, xs[p + 2], 0.75f * x0);
        float y  = 0.5f * (u0 + u1);
        y += (1.f - __cosf(aa * u0)) * bi;
        y += (1.f - __cosf(aa * u1)) * bi;
        ro[p] = y;
    }
    out4[idx4] = r;
}

// ---------------- kernel 3: K=3 conv, packed f32x2 implicit GEMM -------------
// Block tile: 64 co x 128 t. Thread tile: 4 co (stride 16) x 4 t-pairs (stride 32).
// A tile staged twice (copy1 shifted by 1 float) so every tap reads an aligned
// f32 pair. Weights staged pre-duplicated as float2{w,w}.
#define BT   128
#define BCO  64
#define CIC  16
#define AST  132   // padded row stride for A tiles (130 used)

__global__ __launch_bounds__(256)
void conv3_kernel(const float* __restrict__ A, const float* __restrict__ W,
                  const float* __restrict__ bias, const float* __restrict__ resid,
                  float* __restrict__ out)
{
    __shared__ float  As0[CIC][AST];        // col c ->  in[t0-1+c]
    __shared__ float  As1[CIC][AST];        // As1[c] = As0[c+1]
    __shared__ float2 Ws2[CIC*KW][BCO];     // [ci*3+k][co] = {w,w}

    const int b   = blockIdx.z;
    const int co0 = blockIdx.y * BCO;
    const int t0  = blockIdx.x * BT;
    const int tid = threadIdx.x;
    const int tx  = tid & 15;     // t-pair group
    const int ty  = tid >> 4;     // co group

    const float* Ab = A + (b * CCH) * TT;

    uint32_t s_as0 = (uint32_t)__cvta_generic_to_shared(&As0[0][0]);
    uint32_t s_as1 = (uint32_t)__cvta_generic_to_shared(&As1[0][0]);
    uint32_t s_ws  = (uint32_t)__cvta_generic_to_shared(&Ws2[0][0]);

    // accumulators init with bias (packed into both lanes)
    ull acc[4][4];
#pragma unroll
    for (int i = 0; i < 4; i++) {
        float bb = bias[co0 + ty + 16 * i];
        ull bp = pack2(bb, bb);
#pragma unroll
        for (int j = 0; j < 4; j++) acc[i][j] = bp;
    }

    const int ar = tid >> 4;   // A staging row (0..15)
    const int al = tid & 15;   // A staging lane

    for (int ci0 = 0; ci0 < CCH; ci0 += CIC) {
        // ---- stage A (both copies from one global load) ----
        {
            const float* arow = Ab + (ci0 + ar) * TT;
#pragma unroll
            for (int c = al; c < BT + 2; c += 16) {
                int t = t0 - 1 + c;
                float v = (t >= 0 && t < TT) ? arow[t] : 0.f;
                As0[ar][c] = v;
                if (c > 0) As1[ar][c - 1] = v;
            }
        }
        // ---- stage W duplicated ----
        {
            const float* wbase = W + ci0 * KW;
#pragma unroll
            for (int idx = tid; idx < BCO * CIC * KW; idx += 256) {
                int co   = idx / (CIC * KW);
                int rest = idx - co * (CIC * KW);     // ci*3 + k
                float w = wbase[(co0 + co) * (CCH * KW) + rest];
                Ws2[rest][co] = make_float2(w, w);
            }
        }
        __syncthreads();

#pragma unroll
        for (int ci = 0; ci < CIC; ci++) {
            ull a0[4], a1[4], a2v[4];
#pragma unroll
            for (int j = 0; j < 4; j++) {
                int lt = 2 * tx + 32 * j;
                uint32_t o0 = (uint32_t)((ci * AST + lt) * 4);
                a0[j]  = lds64(s_as0 + o0);       // {in[t-1], in[t]}
                a1[j]  = lds64(s_as1 + o0);       // {in[t],   in[t+1]}
                a2v[j] = lds64(s_as0 + o0 + 8);   // {in[t+1], in[t+2]}
            }
#pragma unroll
            for (int i = 0; i < 4; i++) {
                uint32_t wo = s_ws + (uint32_t)(((ci * KW) * BCO + (ty + 16 * i)) * 8);
                ull w0 = lds64(wo);
                ull w1 = lds64(wo + BCO * 8);
                ull w2 = lds64(wo + 2 * BCO * 8);
#pragma unroll
                for (int j = 0; j < 4; j++) {
                    acc[i][j] = ffma2(w0, a0[j],  acc[i][j]);
                    acc[i][j] = ffma2(w1, a1[j],  acc[i][j]);
                    acc[i][j] = ffma2(w2, a2v[j], acc[i][j]);
                }
            }
        }
        __syncthreads();
    }

    // ---- epilogue: (+residual) store float2 pairs ----
#pragma unroll
    for (int i = 0; i < 4; i++) {
        int co = co0 + ty + 16 * i;
#pragma unroll
        for (int j = 0; j < 4; j++) {
            int t   = t0 + 2 * tx + 32 * j;
            int idx = (b * CCH + co) * TT + t;
            float lo, hi;
            unpack2(acc[i][j], lo, hi);
            if (resid) {
                float2 rv = *(const float2*)(resid + idx);
                lo += rv.x; hi += rv.y;
            }
            *(float2*)(out + idx) = make_float2(lo, hi);
        }
    }
}

// ---------------------------------- launch -----------------------------------
extern "C" void kernel_launch(void* const* d_in, const int* in_sizes, int n_in,
                              void* d_out, int out_size)
{
    const float* x      = (const float*)d_in[0];
    const float* v1     = (const float*)d_in[1];
    const float* g1     = (const float*)d_in[2];
    const float* bias1  = (const float*)d_in[3];
    const float* v2     = (const float*)d_in[4];
    const float* g2     = (const float*)d_in[5];
    const float* bias2  = (const float*)d_in[6];
    const float* alpha1 = (const float*)d_in[7];
    const float* beta1  = (const float*)d_in[8];
    const float* alpha2 = (const float*)d_in[9];
    const float* beta2  = (const float*)d_in[10];
    float* out = (float*)d_out;

    float *w1, *w2, *act, *c1, *a2c, *binv;
    cudaGetSymbolAddress((void**)&w1,   g_w1);
    cudaGetSymbolAddress((void**)&w2,   g_w2);
    cudaGetSymbolAddress((void**)&act,  g_act);
    cudaGetSymbolAddress((void**)&c1,   g_c1);
    cudaGetSymbolAddress((void**)&a2c,  g_a2c);
    cudaGetSymbolAddress((void**)&binv, g_binv);

    wnorm_kernel<<<CCH, 256>>>(v1, g1, w1, alpha1, beta1, a2c,       binv);
    wnorm_kernel<<<CCH, 256>>>(v2, g2, w2, alpha2, beta2, a2c + CCH, binv + CCH);

    snake_act_kernel<<<NEL / 4 / 256, 256>>>((const float4*)x, x, a2c, binv, (float4*)act);

    dim3 cgrid(TT / BT, CCH / BCO, BSZ);
    conv3_kernel<<<cgrid, 256>>>(act, w1, bias1, nullptr, c1);

    snake_act_kernel<<<NEL / 4 / 256, 256>>>((const float4*)c1, c1, a2c + CCH, binv + CCH,
                                             (float4*)act);

    conv3_kernel<<<cgrid, 256>>>(act, w2, bias2, x, out);
}

// round 5
// speedup vs baseline: 4.0128x; 4.0128x over previous
#include <cuda_runtime.h>
#include <cuda_bf16.h>
#include <math.h>
#include <stdint.h>

#define BSZ 8
#define CCH 512
#define TT  8192
#define NEL (BSZ*CCH*TT)
#define KW  3

// ---- conv tiling ----
#define MCO 128
#define NTT 128
#define CC  32                   // ci per pipeline stage
#define NCHUNK (CCH/CC)          // 16
#define ROWB 80                  // smem row stride bytes (32 bf16 = 64B data + pad)
#define A_TILE (128*ROWB)        // 10240
#define B_TILE (136*ROWB)        // 10880
#define SM_BOFF (6*A_TILE)       // 61440
#define STAGE (6*A_TILE + 2*B_TILE) // 83200
#define SM_TOTAL (2*STAGE)       // 166400

// ---------------- scratch ------------------------------------------------------
__device__ __nv_bfloat16 g_actT_hi[NEL];      // [b][t][ci]
__device__ __nv_bfloat16 g_actT_lo[NEL];
__device__ float         g_c1[NEL];           // conv1 out [b][co][t]
__device__ __nv_bfloat16 g_wsp1[2*3*CCH*CCH]; // [(split*3+tap)][co][ci]
__device__ __nv_bfloat16 g_wsp2[2*3*CCH*CCH];
__device__ float g_a2c[2*CCH];
__device__ float g_binv[2*CCH];

// ---------------- PTX helpers ---------------------------------------------------
__device__ __forceinline__ void cp16(uint32_t dst, const void* src, bool pred) {
    asm volatile("cp.async.ca.shared.global [%0], [%1], 16, %2;"
                 :: "r"(dst), "l"(src), "r"(pred ? 16 : 0));
}
__device__ __forceinline__ void cp_commit() { asm volatile("cp.async.commit_group;"); }
template<int N> __device__ __forceinline__ void cp_wait() {
    asm volatile("cp.async.wait_group %0;" :: "n"(N));
}
__device__ __forceinline__ void ldx4(uint32_t* r, uint32_t addr) {
    asm volatile("ldmatrix.sync.aligned.m8n8.x4.shared.b16 {%0,%1,%2,%3}, [%4];"
                 : "=r"(r[0]), "=r"(r[1]), "=r"(r[2]), "=r"(r[3]) : "r"(addr));
}
__device__ __forceinline__ void ldx2(uint32_t* r, uint32_t addr) {
    asm volatile("ldmatrix.sync.aligned.m8n8.x2.shared.b16 {%0,%1}, [%2];"
                 : "=r"(r[0]), "=r"(r[1]) : "r"(addr));
}
__device__ __forceinline__ void mma16816(float* d, const uint32_t* a, const uint32_t* b) {
    asm volatile(
        "mma.sync.aligned.m16n8k16.row.col.f32.bf16.bf16.f32 "
        "{%0,%1,%2,%3}, {%4,%5,%6,%7}, {%8,%9}, {%0,%1,%2,%3};"
        : "+f"(d[0]), "+f"(d[1]), "+f"(d[2]), "+f"(d[3])
        : "r"(a[0]), "r"(a[1]), "r"(a[2]), "r"(a[3]), "r"(b[0]), "r"(b[1]));
}

// ---------------- kernel 1: weight norm + bf16 hi/lo split ----------------------
__global__ void wnorm_split_kernel(const float* __restrict__ v, const float* __restrict__ g,
                                   const float* __restrict__ alpha, const float* __restrict__ beta,
                                   __nv_bfloat16* __restrict__ wsp,
                                   float* __restrict__ a2out, float* __restrict__ binvout)
{
    int co = blockIdx.x;
    const float* vc = v + co * (CCH * KW);
    float s = 0.f;
    for (int i = threadIdx.x; i < CCH * KW; i += 256) { float t = vc[i]; s += t * t; }
    __shared__ float red[256];
    red[threadIdx.x] = s;
    __syncthreads();
    for (int off = 128; off > 0; off >>= 1) {
        if (threadIdx.x < off) red[threadIdx.x] += red[threadIdx.x + off];
        __syncthreads();
    }
    float scale = g[co] / sqrtf(red[0]);
    for (int i = threadIdx.x; i < CCH * KW; i += 256) {
        int ci = i / KW, k = i % KW;
        float wn = vc[i] * scale;
        __nv_bfloat16 hi = __float2bfloat16(wn);
        float lof = wn - __bfloat162float(hi);
        wsp[((size_t)(0 * 3 + k) * CCH + co) * CCH + ci] = hi;
        wsp[((size_t)(1 * 3 + k) * CCH + co) * CCH + ci] = __float2bfloat16(lof);
    }
    if (threadIdx.x == 0) {
        a2out[co]   = 2.f * expf(alpha[co]);
        binvout[co] = 1.f / (2.f * expf(beta[co]) + 1e-9f);
    }
}

// ---------------- kernel 2: SnakeBeta Activation1d + transpose + split ----------
#define ATI 64
#define ATT 64
__global__ __launch_bounds__(256)
void snake_actT_kernel(const float* __restrict__ in,
                       const float* __restrict__ a2,
                       const float* __restrict__ binv,
                       __nv_bfloat16* __restrict__ oHi,
                       __nv_bfloat16* __restrict__ oLo)
{
    __shared__ float xs[ATI][ATT + 3];
    int tid = threadIdx.x;
    int b = blockIdx.z, ci0 = blockIdx.y * ATI, t0 = blockIdx.x * ATT;
    const float* xb = in + ((size_t)b * CCH + ci0) * TT;

    for (int e = tid; e < ATI * (ATT + 2); e += 256) {
        int r = e / (ATT + 2);
        int c = e - r * (ATT + 2);
        int t = t0 - 1 + c;
        float v;
        if (t < 0)        v = 0.f;
        else if (t >= TT) v = xb[r * TT + (TT - 1)];
        else              v = xb[r * TT + t];
        xs[r][c] = v;
    }
    __syncthreads();

    int w = tid >> 5, l = tid & 31;
    int ci = (w & 1) * 32 + l;
    int wt = w >> 1;
    float aa = a2[ci0 + ci];
    float bi = 0.5f * binv[ci0 + ci];
#pragma unroll 4
    for (int s = 0; s < 16; s++) {
        int tl = wt * 16 + s;
        int t  = t0 + tl;
        float xm = xs[ci][tl], x0 = xs[ci][tl + 1], xp = xs[ci][tl + 2];
        float u0 = (t > 0) ? fmaf(0.25f, xm, 0.75f * x0) : x0;
        float u1 = fmaf(0.25f, xp, 0.75f * x0);
        float y  = 0.5f * (u0 + u1)
                 + (1.f - __cosf(aa * u0)) * bi
                 + (1.f - __cosf(aa * u1)) * bi;
        size_t oidx = ((size_t)b * TT + t) * CCH + ci0 + ci;
        __nv_bfloat16 hi = __float2bfloat16(y);
        oHi[oidx] = hi;
        oLo[oidx] = __float2bfloat16(y - __bfloat162float(hi));
    }
}

// ---------------- kernel 3: conv via mma.sync bf16, 3-term split ----------------
// out[co,t] = sum_{ci,tap} W_tap[co,ci] * act[t+tap-1, ci]
// smem stage: A = 6 tiles (hi/lo x 3 taps) [128co][32ci]; B = 2 tiles [136t][32ci].
__global__ __launch_bounds__(256, 1)
void conv_mma_kernel(const __nv_bfloat16* __restrict__ aHi,
                     const __nv_bfloat16* __restrict__ aLo,
                     const __nv_bfloat16* __restrict__ Wsp,
                     const float* __restrict__ bias,
                     const float* __restrict__ resid,
                     float* __restrict__ out)
{
    extern __shared__ char smem[];
    const uint32_t sbase = (uint32_t)__cvta_generic_to_shared(smem);
    const int tid  = threadIdx.x;
    const int wid  = tid >> 5, lane = tid & 31;
    const int wco  = wid & 1, wt = wid >> 1;
    const int gid  = lane >> 2, tig = lane & 3;
    const int b    = blockIdx.z;
    const int co0  = blockIdx.y * MCO;
    const int t0   = blockIdx.x * NTT;

    float acc[4][4][4];
#pragma unroll
    for (int m = 0; m < 4; m++)
#pragma unroll
        for (int n = 0; n < 4; n++)
#pragma unroll
            for (int q = 0; q < 4; q++) acc[m][n][q] = 0.f;

    // ---- stage issue: chunk ch -> buffer ch&1 ----
    auto issue = [&](int ch) {
        const int ci0 = ch * CC;
        const uint32_t sb = sbase + (uint32_t)(ch & 1) * STAGE;
        for (int u = tid; u < 6 * 128 * 4 + 2 * 136 * 4; u += 256) {
            if (u < 3072) {
                int tile = u >> 9;
                int rem  = u & 511;
                int row  = rem >> 2;
                int seg  = rem & 3;
                const __nv_bfloat16* src =
                    Wsp + ((size_t)(tile * CCH + co0 + row)) * CCH + ci0 + seg * 8;
                cp16(sb + tile * A_TILE + row * ROWB + seg * 16, src, true);
            } else {
                int u2   = u - 3072;
                int tile = u2 / 544;
                int rem  = u2 - tile * 544;
                int row  = rem >> 2;
                int seg  = rem & 3;
                int t    = t0 - 1 + row;
                bool ok  = (t >= 0 && t < TT && row < 130);
                int tc   = ok ? t : 0;
                const __nv_bfloat16* src = (tile ? aLo : aHi)
                    + ((size_t)b * TT + tc) * CCH + ci0 + seg * 8;
                cp16(sb + SM_BOFF + tile * B_TILE + row * ROWB + seg * 16, src, ok);
            }
        }
        cp_commit();
    };

    issue(0);
    issue(1);

    const int arow  = wco * 64 + (lane & 15);        // A ldmatrix row within tile
    const int akoff = (lane >> 4) * 16;              // k-half byte offset
    const int brow  = lane & 7;                      // B ldmatrix row offset
    const int bkoff = ((lane >> 3) & 1) * 16;

    for (int ch = 0; ch < NCHUNK; ch++) {
        if (ch < NCHUNK - 1) cp_wait<1>(); else cp_wait<0>();
        __syncthreads();

        const uint32_t sb = sbase + (uint32_t)(ch & 1) * STAGE;
#pragma unroll
        for (int ks = 0; ks < 2; ks++) {
            // B fragments: hi/lo x 3 taps x 4 n
            uint32_t bh[3][4][2], bl[3][4][2];
#pragma unroll
            for (int tap = 0; tap < 3; tap++)
#pragma unroll
                for (int n = 0; n < 4; n++) {
                    int rbase = wt * 32 + n * 8 + tap;   // t_local + tap (halo offset +1, shift -1)
                    uint32_t ba = sb + SM_BOFF + (rbase + brow) * ROWB + bkoff + ks * 32;
                    ldx2(bh[tap][n], ba);
                    ldx2(bl[tap][n], ba + B_TILE);
                }
#pragma unroll
            for (int tap = 0; tap < 3; tap++) {
#pragma unroll
                for (int m = 0; m < 4; m++) {
                    uint32_t aoff = (uint32_t)((arow + m * 16) * ROWB + akoff + ks * 32);
                    uint32_t ah[4], al[4];
                    ldx4(ah, sb + tap * A_TILE + aoff);
#pragma unroll
                    for (int n = 0; n < 4; n++) mma16816(acc[m][n], ah, bh[tap][n]);
#pragma unroll
                    for (int n = 0; n < 4; n++) mma16816(acc[m][n], ah, bl[tap][n]);
                    ldx4(al, sb + (3 + tap) * A_TILE + aoff);
#pragma unroll
                    for (int n = 0; n < 4; n++) mma16816(acc[m][n], al, bh[tap][n]);
                }
            }
        }
        __syncthreads();
        if (ch + 2 < NCHUNK) issue(ch + 2);
    }

    // ---- epilogue ----
#pragma unroll
    for (int m = 0; m < 4; m++) {
        int r0 = co0 + wco * 64 + m * 16 + gid;
        int r1 = r0 + 8;
        float b0 = bias[r0], b1 = bias[r1];
        size_t o0 = ((size_t)(b * CCH + r0)) * TT + t0;
        size_t o1 = ((size_t)(b * CCH + r1)) * TT + t0;
#pragma unroll
        for (int n = 0; n < 4; n++) {
            int tof = wt * 32 + n * 8 + 2 * tig;
            float2 v0 = make_float2(acc[m][n][0] + b0, acc[m][n][1] + b0);
            float2 v1 = make_float2(acc[m][n][2] + b1, acc[m][n][3] + b1);
            if (resid) {
                float2 rv0 = *(const float2*)(resid + o0 + tof);
                float2 rv1 = *(const float2*)(resid + o1 + tof);
                v0.x += rv0.x; v0.y += rv0.y;
                v1.x += rv1.x; v1.y += rv1.y;
            }
            *(float2*)(out + o0 + tof) = v0;
            *(float2*)(out + o1 + tof) = v1;
        }
    }
}

// ---------------------------------- launch ---------------------------------------
extern "C" void kernel_launch(void* const* d_in, const int* in_sizes, int n_in,
                              void* d_out, int out_size)
{
    const float* x      = (const float*)d_in[0];
    const float* v1     = (const float*)d_in[1];
    const float* g1     = (const float*)d_in[2];
    const float* bias1  = (const float*)d_in[3];
    const float* v2     = (const float*)d_in[4];
    const float* g2     = (const float*)d_in[5];
    const float* bias2  = (const float*)d_in[6];
    const float* alpha1 = (const float*)d_in[7];
    const float* beta1  = (const float*)d_in[8];
    const float* alpha2 = (const float*)d_in[9];
    const float* beta2  = (const float*)d_in[10];
    float* out = (float*)d_out;

    __nv_bfloat16 *aHi, *aLo, *w1, *w2;
    float *c1, *a2c, *binv;
    cudaGetSymbolAddress((void**)&aHi,  g_actT_hi);
    cudaGetSymbolAddress((void**)&aLo,  g_actT_lo);
    cudaGetSymbolAddress((void**)&c1,   g_c1);
    cudaGetSymbolAddress((void**)&w1,   g_wsp1);
    cudaGetSymbolAddress((void**)&w2,   g_wsp2);
    cudaGetSymbolAddress((void**)&a2c,  g_a2c);
    cudaGetSymbolAddress((void**)&binv, g_binv);

    static bool attr_set = false;
    if (!attr_set) {
        cudaFuncSetAttribute(conv_mma_kernel,
                             cudaFuncAttributeMaxDynamicSharedMemorySize, SM_TOTAL);
        attr_set = true;
    }

    wnorm_split_kernel<<<CCH, 256>>>(v1, g1, alpha1, beta1, w1, a2c,       binv);
    wnorm_split_kernel<<<CCH, 256>>>(v2, g2, alpha2, beta2, w2, a2c + CCH, binv + CCH);

    dim3 agrid(TT / ATT, CCH / ATI, BSZ);
    dim3 cgrid(TT / NTT, CCH / MCO, BSZ);

    snake_actT_kernel<<<agrid, 256>>>(x, a2c, binv, aHi, aLo);
    conv_mma_kernel<<<cgrid, 256, SM_TOTAL>>>(aHi, aLo, w1, bias1, nullptr, c1);
    snake_actT_kernel<<<agrid, 256>>>(c1, a2c + CCH, binv + CCH, aHi, aLo);
    conv_mma_kernel<<<cgrid, 256, SM_TOTAL>>>(aHi, aLo, w2, bias2, x, out);
}

// round 6
// speedup vs baseline: 8.8921x; 2.2160x over previous
#include <cuda_runtime.h>
#include <cuda_fp16.h>
#include <math.h>
#include <stdint.h>

#define BSZ 8
#define CCH 512
#define TT  8192
#define NEL (BSZ*CCH*TT)
#define KW  3

// ---- conv tiling ----
#define MCO 128
#define NTT 128
#define CC  64                       // ci per pipeline stage
#define NCHUNK (CCH/CC)              // 8
#define ROWB 144                     // 64 fp16 = 128B data + 16B pad (conflict-free ldmatrix)
#define A_TILE (128*ROWB)            // 18432
#define B_TILE (136*ROWB)            // 19584
#define SM_BOFF (3*A_TILE)           // 55296
#define STAGE (3*A_TILE + B_TILE)    // 74880
#define SM_TOTAL (2*STAGE)           // 149760

// ---------------- scratch ------------------------------------------------------
__device__ __half g_actT[NEL];            // [b][t][ci] fp16
__device__ float  g_c1[NEL];              // conv1 out [b][co][t]
__device__ __half g_w1[3*CCH*CCH];        // [tap][co][ci] fp16
__device__ __half g_w2[3*CCH*CCH];
__device__ float  g_a2c[2*CCH];
__device__ float  g_binv[2*CCH];

// ---------------- PTX helpers ---------------------------------------------------
__device__ __forceinline__ void cp16(uint32_t dst, const void* src, bool pred) {
    asm volatile("cp.async.ca.shared.global [%0], [%1], 16, %2;"
                 :: "r"(dst), "l"(src), "r"(pred ? 16 : 0));
}
__device__ __forceinline__ void cp_commit() { asm volatile("cp.async.commit_group;"); }
template<int N> __device__ __forceinline__ void cp_wait() {
    asm volatile("cp.async.wait_group %0;" :: "n"(N));
}
__device__ __forceinline__ void ldx4(uint32_t* r, uint32_t addr) {
    asm volatile("ldmatrix.sync.aligned.m8n8.x4.shared.b16 {%0,%1,%2,%3}, [%4];"
                 : "=r"(r[0]), "=r"(r[1]), "=r"(r[2]), "=r"(r[3]) : "r"(addr));
}
__device__ __forceinline__ void ldx2(uint32_t* r, uint32_t addr) {
    asm volatile("ldmatrix.sync.aligned.m8n8.x2.shared.b16 {%0,%1}, [%2];"
                 : "=r"(r[0]), "=r"(r[1]) : "r"(addr));
}
__device__ __forceinline__ void mma16816(float* d, const uint32_t* a, const uint32_t* b) {
    asm volatile(
        "mma.sync.aligned.m16n8k16.row.col.f32.f16.f16.f32 "
        "{%0,%1,%2,%3}, {%4,%5,%6,%7}, {%8,%9}, {%0,%1,%2,%3};"
        : "+f"(d[0]), "+f"(d[1]), "+f"(d[2]), "+f"(d[3])
        : "r"(a[0]), "r"(a[1]), "r"(a[2]), "r"(a[3]), "r"(b[0]), "r"(b[1]));
}

// ---------------- kernel 1: weight norm -> fp16 [tap][co][ci] -------------------
__global__ void wnorm_kernel(const float* __restrict__ v, const float* __restrict__ g,
                             const float* __restrict__ alpha, const float* __restrict__ beta,
                             __half* __restrict__ wsp,
                             float* __restrict__ a2out, float* __restrict__ binvout)
{
    int co = blockIdx.x;
    const float* vc = v + co * (CCH * KW);
    float s = 0.f;
    for (int i = threadIdx.x; i < CCH * KW; i += 256) { float t = vc[i]; s += t * t; }
    __shared__ float red[256];
    red[threadIdx.x] = s;
    __syncthreads();
    for (int off = 128; off > 0; off >>= 1) {
        if (threadIdx.x < off) red[threadIdx.x] += red[threadIdx.x + off];
        __syncthreads();
    }
    float scale = g[co] / sqrtf(red[0]);
    for (int i = threadIdx.x; i < CCH * KW; i += 256) {
        int ci = i / KW, k = i % KW;
        wsp[((size_t)k * CCH + co) * CCH + ci] = __float2half(vc[i] * scale);
    }
    if (threadIdx.x == 0) {
        a2out[co]   = 2.f * expf(alpha[co]);
        binvout[co] = 1.f / (2.f * expf(beta[co]) + 1e-9f);
    }
}

// ---------------- kernel 2: SnakeBeta Activation1d + transpose -> fp16 ----------
#define ATI 64
#define ATT 64
__global__ __launch_bounds__(256)
void snake_actT_kernel(const float* __restrict__ in,
                       const float* __restrict__ a2,
                       const float* __restrict__ binv,
                       __half* __restrict__ oA)
{
    __shared__ float xs[ATI][ATT + 3];
    int tid = threadIdx.x;
    int b = blockIdx.z, ci0 = blockIdx.y * ATI, t0 = blockIdx.x * ATT;
    const float* xb = in + ((size_t)b * CCH + ci0) * TT;

    for (int e = tid; e < ATI * (ATT + 2); e += 256) {
        int r = e / (ATT + 2);
        int c = e - r * (ATT + 2);
        int t = t0 - 1 + c;
        float v;
        if (t < 0)        v = 0.f;
        else if (t >= TT) v = xb[r * TT + (TT - 1)];
        else              v = xb[r * TT + t];
        xs[r][c] = v;
    }
    __syncthreads();

    int w = tid >> 5, l = tid & 31;
    int ci = (w & 1) * 32 + l;
    int wt = w >> 1;
    float aa = a2[ci0 + ci];
    float bi = 0.5f * binv[ci0 + ci];
#pragma unroll 4
    for (int s = 0; s < 16; s++) {
        int tl = wt * 16 + s;
        int t  = t0 + tl;
        float xm = xs[ci][tl], x0 = xs[ci][tl + 1], xp = xs[ci][tl + 2];
        float u0 = (t > 0) ? fmaf(0.25f, xm, 0.75f * x0) : x0;
        float u1 = fmaf(0.25f, xp, 0.75f * x0);
        float y  = 0.5f * (u0 + u1)
                 + (1.f - __cosf(aa * u0)) * bi
                 + (1.f - __cosf(aa * u1)) * bi;
        oA[((size_t)b * TT + t) * CCH + ci0 + ci] = __float2half(y);
    }
}

// ---------------- kernel 3: conv via mma.sync fp16, single pass -----------------
// out[co,t] = sum_{ci,tap} W_tap[co,ci] * act[t+tap-1, ci]
__global__ __launch_bounds__(256, 1)
void conv_mma_kernel(const __half* __restrict__ aA,
                     const __half* __restrict__ Wsp,
                     const float* __restrict__ bias,
                     const float* __restrict__ resid,
                     float* __restrict__ out)
{
    extern __shared__ char smem[];
    const uint32_t sbase = (uint32_t)__cvta_generic_to_shared(smem);
    const int tid  = threadIdx.x;
    const int wid  = tid >> 5, lane = tid & 31;
    const int wco  = wid & 1, wt = wid >> 1;
    const int gid  = lane >> 2, tig = lane & 3;
    const int b    = blockIdx.z;
    const int co0  = blockIdx.y * MCO;
    const int t0   = blockIdx.x * NTT;

    float acc[4][4][4];
#pragma unroll
    for (int m = 0; m < 4; m++)
#pragma unroll
        for (int n = 0; n < 4; n++)
#pragma unroll
            for (int q = 0; q < 4; q++) acc[m][n][q] = 0.f;

    // ---- stage issue: chunk ch -> buffer ch&1 ----
    // A: 3 tap tiles [128co][64ci] = 3*128*8 segs; B: [136t][64ci] = 136*8 segs
    auto issue = [&](int ch) {
        const int ci0 = ch * CC;
        const uint32_t sb = sbase + (uint32_t)(ch & 1) * STAGE;
        for (int u = tid; u < 3 * 128 * 8 + 136 * 8; u += 256) {
            if (u < 3072) {
                int tile = u >> 10;
                int rem  = u & 1023;
                int row  = rem >> 3;
                int seg  = rem & 7;
                const __half* src =
                    Wsp + ((size_t)(tile * CCH + co0 + row)) * CCH + ci0 + seg * 8;
                cp16(sb + tile * A_TILE + row * ROWB + seg * 16, src, true);
            } else {
                int u2  = u - 3072;
                int row = u2 >> 3;
                int seg = u2 & 7;
                int t   = t0 - 1 + row;
                bool ok = (t >= 0 && t < TT && row < 130);
                int tc  = ok ? t : 0;
                const __half* src = aA + ((size_t)b * TT + tc) * CCH + ci0 + seg * 8;
                cp16(sb + SM_BOFF + row * ROWB + seg * 16, src, ok);
            }
        }
        cp_commit();
    };

    issue(0);
    issue(1);

    const int arow  = wco * 64 + (lane & 15);
    const int akoff = (lane >> 4) * 16;
    const int brow  = lane & 7;
    const int bkoff = ((lane >> 3) & 1) * 16;

    for (int ch = 0; ch < NCHUNK; ch++) {
        if (ch < NCHUNK - 1) cp_wait<1>(); else cp_wait<0>();
        __syncthreads();

        const uint32_t sb = sbase + (uint32_t)(ch & 1) * STAGE;
#pragma unroll
        for (int ks = 0; ks < 4; ks++) {
            uint32_t bf[3][4][2];
#pragma unroll
            for (int tap = 0; tap < 3; tap++)
#pragma unroll
                for (int n = 0; n < 4; n++) {
                    int rbase = wt * 32 + n * 8 + tap;
                    ldx2(bf[tap][n],
                         sb + SM_BOFF + (rbase + brow) * ROWB + bkoff + ks * 32);
                }
#pragma unroll
            for (int tap = 0; tap < 3; tap++) {
#pragma unroll
                for (int m = 0; m < 4; m++) {
                    uint32_t af[4];
                    ldx4(af, sb + tap * A_TILE
                              + (uint32_t)((arow + m * 16) * ROWB + akoff + ks * 32));
#pragma unroll
                    for (int n = 0; n < 4; n++) mma16816(acc[m][n], af, bf[tap][n]);
                }
            }
        }
        __syncthreads();
        if (ch + 2 < NCHUNK) issue(ch + 2);
    }

    // ---- epilogue ----
#pragma unroll
    for (int m = 0; m < 4; m++) {
        int r0 = co0 + wco * 64 + m * 16 + gid;
        int r1 = r0 + 8;
        float b0 = bias[r0], b1 = bias[r1];
        size_t o0 = ((size_t)(b * CCH + r0)) * TT + t0;
        size_t o1 = ((size_t)(b * CCH + r1)) * TT + t0;
#pragma unroll
        for (int n = 0; n < 4; n++) {
            int tof = wt * 32 + n * 8 + 2 * tig;
            float2 v0 = make_float2(acc[m][n][0] + b0, acc[m][n][1] + b0);
            float2 v1 = make_float2(acc[m][n][2] + b1, acc[m][n][3] + b1);
            if (resid) {
                float2 rv0 = *(const float2*)(resid + o0 + tof);
                float2 rv1 = *(const float2*)(resid + o1 + tof);
                v0.x += rv0.x; v0.y += rv0.y;
                v1.x += rv1.x; v1.y += rv1.y;
            }
            *(float2*)(out + o0 + tof) = v0;
            *(float2*)(out + o1 + tof) = v1;
        }
    }
}

// ---------------------------------- launch ---------------------------------------
extern "C" void kernel_launch(void* const* d_in, const int* in_sizes, int n_in,
                              void* d_out, int out_size)
{
    const float* x      = (const float*)d_in[0];
    const float* v1     = (const float*)d_in[1];
    const float* g1     = (const float*)d_in[2];
    const float* bias1  = (const float*)d_in[3];
    const float* v2     = (const float*)d_in[4];
    const float* g2     = (const float*)d_in[5];
    const float* bias2  = (const float*)d_in[6];
    const float* alpha1 = (const float*)d_in[7];
    const float* beta1  = (const float*)d_in[8];
    const float* alpha2 = (const float*)d_in[9];
    const float* beta2  = (const float*)d_in[10];
    float* out = (float*)d_out;

    __half *aA, *w1, *w2;
    float *c1, *a2c, *binv;
    cudaGetSymbolAddress((void**)&aA,   g_actT);
    cudaGetSymbolAddress((void**)&c1,   g_c1);
    cudaGetSymbolAddress((void**)&w1,   g_w1);
    cudaGetSymbolAddress((void**)&w2,   g_w2);
    cudaGetSymbolAddress((void**)&a2c,  g_a2c);
    cudaGetSymbolAddress((void**)&binv, g_binv);

    static bool attr_set = false;
    if (!attr_set) {
        cudaFuncSetAttribute(conv_mma_kernel,
                             cudaFuncAttributeMaxDynamicSharedMemorySize, SM_TOTAL);
        attr_set = true;
    }

    wnorm_kernel<<<CCH, 256>>>(v1, g1, alpha1, beta1, w1, a2c,       binv);
    wnorm_kernel<<<CCH, 256>>>(v2, g2, alpha2, beta2, w2, a2c + CCH, binv + CCH);

    dim3 agrid(TT / ATT, CCH / ATI, BSZ);
    dim3 cgrid(TT / NTT, CCH / MCO, BSZ);

    snake_actT_kernel<<<agrid, 256>>>(x, a2c, binv, aA);
    conv_mma_kernel<<<cgrid, 256, SM_TOTAL>>>(aA, w1, bias1, nullptr, c1);
    snake_actT_kernel<<<agrid, 256>>>(c1, a2c + CCH, binv + CCH, aA);
    conv_mma_kernel<<<cgrid, 256, SM_TOTAL>>>(aA, w2, bias2, x, out);
}

// round 7
// speedup vs baseline: 9.3696x; 1.0537x over previous
#include <cuda_runtime.h>
#include <cuda_fp16.h>
#include <math.h>
#include <stdint.h>

#define BSZ 8
#define CCH 512
#define TT  8192
#define NEL (BSZ*CCH*TT)
#define KW  3

// ---- conv tiling ----
#define MCO 128
#define NTT 128
#define CC  32                       // ci per pipeline stage
#define NCHUNK (CCH/CC)              // 16
#define ROWB 80                      // 32 fp16 = 64B data + 16B pad
#define A_TILE (128*ROWB)            // 10240
#define B_TILE (136*ROWB)            // 10880
#define SM_BOFF (3*A_TILE)           // 30720
#define STAGE (3*A_TILE + B_TILE)    // 41600
#define SM_TOTAL (2*STAGE)           // 83200 per CTA (2 CTAs/SM)

// ---------------- scratch ------------------------------------------------------
__device__ __half g_actT[NEL];            // [b][t][ci] fp16
__device__ float  g_c1[NEL];              // conv1 out [b][co][t]
__device__ __half g_w1[3*CCH*CCH];        // [tap][co][ci] fp16
__device__ __half g_w2[3*CCH*CCH];
__device__ float  g_a2c[2*CCH];
__device__ float  g_binv[2*CCH];

// ---------------- PTX helpers ---------------------------------------------------
__device__ __forceinline__ void cp16(uint32_t dst, const void* src, bool pred) {
    asm volatile("cp.async.ca.shared.global [%0], [%1], 16, %2;"
                 :: "r"(dst), "l"(src), "r"(pred ? 16 : 0));
}
__device__ __forceinline__ void cp_commit() { asm volatile("cp.async.commit_group;"); }
template<int N> __device__ __forceinline__ void cp_wait() {
    asm volatile("cp.async.wait_group %0;" :: "n"(N));
}
__device__ __forceinline__ void ldx4(uint32_t* r, uint32_t addr) {
    asm volatile("ldmatrix.sync.aligned.m8n8.x4.shared.b16 {%0,%1,%2,%3}, [%4];"
                 : "=r"(r[0]), "=r"(r[1]), "=r"(r[2]), "=r"(r[3]) : "r"(addr));
}
__device__ __forceinline__ void mma16816(float* d, const uint32_t* a, const uint32_t* b) {
    asm volatile(
        "mma.sync.aligned.m16n8k16.row.col.f32.f16.f16.f32 "
        "{%0,%1,%2,%3}, {%4,%5,%6,%7}, {%8,%9}, {%0,%1,%2,%3};"
        : "+f"(d[0]), "+f"(d[1]), "+f"(d[2]), "+f"(d[3])
        : "r"(a[0]), "r"(a[1]), "r"(a[2]), "r"(a[3]), "r"(b[0]), "r"(b[1]));
}

// ---------------- kernel 1: weight norm -> fp16 [tap][co][ci] -------------------
__global__ void wnorm_kernel(const float* __restrict__ v, const float* __restrict__ g,
                             const float* __restrict__ alpha, const float* __restrict__ beta,
                             __half* __restrict__ wsp,
                             float* __restrict__ a2out, float* __restrict__ binvout)
{
    int co = blockIdx.x;
    const float* vc = v + co * (CCH * KW);
    float s = 0.f;
    for (int i = threadIdx.x; i < CCH * KW; i += 256) { float t = vc[i]; s += t * t; }
    __shared__ float red[256];
    red[threadIdx.x] = s;
    __syncthreads();
    for (int off = 128; off > 0; off >>= 1) {
        if (threadIdx.x < off) red[threadIdx.x] += red[threadIdx.x + off];
        __syncthreads();
    }
    float scale = g[co] / sqrtf(red[0]);
    for (int i = threadIdx.x; i < CCH * KW; i += 256) {
        int ci = i / KW, k = i % KW;
        wsp[((size_t)k * CCH + co) * CCH + ci] = __float2half(vc[i] * scale);
    }
    if (threadIdx.x == 0) {
        a2out[co]   = 2.f * expf(alpha[co]);
        binvout[co] = 1.f / (2.f * expf(beta[co]) + 1e-9f);
    }
}

// ---------------- kernel 2: SnakeBeta Activation1d + transpose -> fp16 ----------
#define ATI 64
#define ATT 64
__global__ __launch_bounds__(256)
void snake_actT_kernel(const float* __restrict__ in,
                       const float* __restrict__ a2,
                       const float* __restrict__ binv,
                       __half* __restrict__ oA)
{
    __shared__ float xs[ATI][ATT + 3];
    int tid = threadIdx.x;
    int b = blockIdx.z, ci0 = blockIdx.y * ATI, t0 = blockIdx.x * ATT;
    const float* xb = in + ((size_t)b * CCH + ci0) * TT;

    for (int e = tid; e < ATI * (ATT + 2); e += 256) {
        int r = e / (ATT + 2);
        int c = e - r * (ATT + 2);
        int t = t0 - 1 + c;
        float v;
        if (t < 0)        v = 0.f;
        else if (t >= TT) v = xb[r * TT + (TT - 1)];
        else              v = xb[r * TT + t];
        xs[r][c] = v;
    }
    __syncthreads();

    int w = tid >> 5, l = tid & 31;
    int ci = (w & 1) * 32 + l;
    int wt = w >> 1;
    float aa = a2[ci0 + ci];
    float bi = 0.5f * binv[ci0 + ci];
#pragma unroll 4
    for (int s = 0; s < 16; s++) {
        int tl = wt * 16 + s;
        int t  = t0 + tl;
        float xm = xs[ci][tl], x0 = xs[ci][tl + 1], xp = xs[ci][tl + 2];
        float u0 = (t > 0) ? fmaf(0.25f, xm, 0.75f * x0) : x0;
        float u1 = fmaf(0.25f, xp, 0.75f * x0);
        float y  = 0.5f * (u0 + u1)
                 + (1.f - __cosf(aa * u0)) * bi
                 + (1.f - __cosf(aa * u1)) * bi;
        oA[((size_t)b * TT + t) * CCH + ci0 + ci] = __float2half(y);
    }
}

// ---------------- kernel 3: conv via mma.sync fp16, 2 CTA/SM --------------------
// out[co,t] = sum_{ci,tap} W_tap[co,ci] * act[t+tap-1, ci]
__global__ __launch_bounds__(256, 2)
void conv_mma_kernel(const __half* __restrict__ aA,
                     const __half* __restrict__ Wsp,
                     const float* __restrict__ bias,
                     const float* __restrict__ resid,
                     float* __restrict__ out)
{
    extern __shared__ char smem[];
    const uint32_t sbase = (uint32_t)__cvta_generic_to_shared(smem);
    const int tid  = threadIdx.x;
    const int wid  = tid >> 5, lane = tid & 31;
    const int wco  = wid & 1, wt = wid >> 1;
    const int gid  = lane >> 2, tig = lane & 3;
    const int b    = blockIdx.z;
    const int co0  = blockIdx.y * MCO;
    const int t0   = blockIdx.x * NTT;

    float acc[4][4][4];
#pragma unroll
    for (int m = 0; m < 4; m++)
#pragma unroll
        for (int n = 0; n < 4; n++)
#pragma unroll
            for (int q = 0; q < 4; q++) acc[m][n][q] = 0.f;

    // ---- stage issue: chunk ch -> buffer ch&1 ----
    // A: 3 tiles [128co][32ci] = 3*128*4 segs; B: [136t][32ci] = 136*4 segs
    auto issue = [&](int ch) {
        const int ci0 = ch * CC;
        const uint32_t sb = sbase + (uint32_t)(ch & 1) * STAGE;
        for (int u = tid; u < 3 * 128 * 4 + 136 * 4; u += 256) {
            if (u < 1536) {
                int tile = u >> 9;
                int rem  = u & 511;
                int row  = rem >> 2;
                int seg  = rem & 3;
                const __half* src =
                    Wsp + ((size_t)(tile * CCH + co0 + row)) * CCH + ci0 + seg * 8;
                cp16(sb + tile * A_TILE + row * ROWB + seg * 16, src, true);
            } else {
                int u2  = u - 1536;
                int row = u2 >> 2;
                int seg = u2 & 3;
                int t   = t0 - 1 + row;
                bool ok = (t >= 0 && t < TT && row < 130);
                int tc  = ok ? t : 0;
                const __half* src = aA + ((size_t)b * TT + tc) * CCH + ci0 + seg * 8;
                cp16(sb + SM_BOFF + row * ROWB + seg * 16, src, ok);
            }
        }
        cp_commit();
    };

    issue(0);
    issue(1);

    const int arow  = wco * 64 + (lane & 15);            // A ldmatrix row
    const int akoff = (lane >> 4) * 16;                  // A k-half
    const int brow  = (lane & 7) + ((lane >> 4) << 3);   // B paired-x4 row offset
    const int bkoff = ((lane >> 3) & 1) * 16;            // B k-half

    for (int ch = 0; ch < NCHUNK; ch++) {
        if (ch < NCHUNK - 1) cp_wait<1>(); else cp_wait<0>();
        __syncthreads();

        const uint32_t sb = sbase + (uint32_t)(ch & 1) * STAGE;
#pragma unroll
        for (int ks = 0; ks < 2; ks++) {
#pragma unroll
            for (int tap = 0; tap < 3; tap++) {
                // paired B: np covers n = 2np, 2np+1 (16 rows per ldx4)
                uint32_t bq[2][4];
#pragma unroll
                for (int np = 0; np < 2; np++) {
                    int rbase = wt * 32 + np * 16 + tap;
                    ldx4(bq[np], sb + SM_BOFF
                                  + (uint32_t)((rbase + brow) * ROWB + bkoff + ks * 32));
                }
#pragma unroll
                for (int m = 0; m < 4; m++) {
                    uint32_t af[4];
                    ldx4(af, sb + tap * A_TILE
                              + (uint32_t)((arow + m * 16) * ROWB + akoff + ks * 32));
                    mma16816(acc[m][0], af, &bq[0][0]);
                    mma16816(acc[m][1], af, &bq[0][2]);
                    mma16816(acc[m][2], af, &bq[1][0]);
                    mma16816(acc[m][3], af, &bq[1][2]);
                }
            }
        }
        __syncthreads();
        if (ch + 2 < NCHUNK) issue(ch + 2);
    }

    // ---- epilogue ----
#pragma unroll
    for (int m = 0; m < 4; m++) {
        int r0 = co0 + wco * 64 + m * 16 + gid;
        int r1 = r0 + 8;
        float b0 = bias[r0], b1 = bias[r1];
        size_t o0 = ((size_t)(b * CCH + r0)) * TT + t0;
        size_t o1 = ((size_t)(b * CCH + r1)) * TT + t0;
#pragma unroll
        for (int n = 0; n < 4; n++) {
            int tof = wt * 32 + n * 8 + 2 * tig;
            float2 v0 = make_float2(acc[m][n][0] + b0, acc[m][n][1] + b0);
            float2 v1 = make_float2(acc[m][n][2] + b1, acc[m][n][3] + b1);
            if (resid) {
                float2 rv0 = *(const float2*)(resid + o0 + tof);
                float2 rv1 = *(const float2*)(resid + o1 + tof);
                v0.x += rv0.x; v0.y += rv0.y;
                v1.x += rv1.x; v1.y += rv1.y;
            }
            *(float2*)(out + o0 + tof) = v0;
            *(float2*)(out + o1 + tof) = v1;
        }
    }
}

// ---------------------------------- launch ---------------------------------------
extern "C" void kernel_launch(void* const* d_in, const int* in_sizes, int n_in,
                              void* d_out, int out_size)
{
    const float* x      = (const float*)d_in[0];
    const float* v1     = (const float*)d_in[1];
    const float* g1     = (const float*)d_in[2];
    const float* bias1  = (const float*)d_in[3];
    const float* v2     = (const float*)d_in[4];
    const float* g2     = (const float*)d_in[5];
    const float* bias2  = (const float*)d_in[6];
    const float* alpha1 = (const float*)d_in[7];
    const float* beta1  = (const float*)d_in[8];
    const float* alpha2 = (const float*)d_in[9];
    const float* beta2  = (const float*)d_in[10];
    float* out = (float*)d_out;

    __half *aA, *w1, *w2;
    float *c1, *a2c, *binv;
    cudaGetSymbolAddress((void**)&aA,   g_actT);
    cudaGetSymbolAddress((void**)&c1,   g_c1);
    cudaGetSymbolAddress((void**)&w1,   g_w1);
    cudaGetSymbolAddress((void**)&w2,   g_w2);
    cudaGetSymbolAddress((void**)&a2c,  g_a2c);
    cudaGetSymbolAddress((void**)&binv, g_binv);

    static bool attr_set = false;
    if (!attr_set) {
        cudaFuncSetAttribute(conv_mma_kernel,
                             cudaFuncAttributeMaxDynamicSharedMemorySize, SM_TOTAL);
        attr_set = true;
    }

    wnorm_kernel<<<CCH, 256>>>(v1, g1, alpha1, beta1, w1, a2c,       binv);
    wnorm_kernel<<<CCH, 256>>>(v2, g2, alpha2, beta2, w2, a2c + CCH, binv + CCH);

    dim3 agrid(TT / ATT, CCH / ATI, BSZ);
    dim3 cgrid(TT / NTT, CCH / MCO, BSZ);

    snake_actT_kernel<<<agrid, 256>>>(x, a2c, binv, aA);
    conv_mma_kernel<<<cgrid, 256, SM_TOTAL>>>(aA, w1, bias1, nullptr, c1);
    snake_actT_kernel<<<agrid, 256>>>(c1, a2c + CCH, binv + CCH, aA);
    conv_mma_kernel<<<cgrid, 256, SM_TOTAL>>>(aA, w2, bias2, x, out);
}